// round 14
// baseline (speedup 1.0000x reference)
#include <cuda_runtime.h>
#include <cuda_bf16.h>
#include <cuda_fp16.h>
#include <cstdint>

#define IN_F 128
#define HID 128
#define NCTX 32
#define ALPHA 0.2f
#define NEG_INF -9000000000000000.0f
#define MAXN 20000

// Scratch (device globals — no allocation allowed)
__device__ __align__(16) float g_u_i[IN_F];
__device__ __align__(16) float g_u_j[IN_F];
__device__ float g_bias;
__device__ float g_s_i[MAXN];
__device__ float g_s_j[MAXN];
__device__ __align__(16) __half g_hf16[(size_t)MAXN * IN_F];   // fp16 feature table
__device__ __align__(16) __half g_wf16[HID * HID];             // fp16 W_j

// ---------------------------------------------------------------------------
// helpers
// ---------------------------------------------------------------------------
__device__ __forceinline__ uint32_t smem_u32(const void* p) {
    return (uint32_t)__cvta_generic_to_shared(p);
}
__device__ __forceinline__ void ldsm_x4(uint32_t* r, uint32_t addr) {
    asm volatile("ldmatrix.sync.aligned.m8n8.x4.shared.b16 {%0,%1,%2,%3}, [%4];"
        : "=r"(r[0]), "=r"(r[1]), "=r"(r[2]), "=r"(r[3]) : "r"(addr));
}
__device__ __forceinline__ void ldsm_x4_t(uint32_t* r, uint32_t addr) {
    asm volatile("ldmatrix.sync.aligned.m8n8.x4.trans.shared.b16 {%0,%1,%2,%3}, [%4];"
        : "=r"(r[0]), "=r"(r[1]), "=r"(r[2]), "=r"(r[3]) : "r"(addr));
}
__device__ __forceinline__ void mma16816h(float* c, const uint32_t* a,
                                          uint32_t b0, uint32_t b1) {
    asm volatile(
        "mma.sync.aligned.m16n8k16.row.col.f32.f16.f16.f32 "
        "{%0,%1,%2,%3}, {%4,%5,%6,%7}, {%8,%9}, {%0,%1,%2,%3};"
        : "+f"(c[0]), "+f"(c[1]), "+f"(c[2]), "+f"(c[3])
        : "r"(a[0]), "r"(a[1]), "r"(a[2]), "r"(a[3]), "r"(b0), "r"(b1));
}
__device__ __forceinline__ void cp_async16(uint32_t smem, const void* gmem) {
    asm volatile("cp.async.cg.shared.global [%0], [%1], 16;"
        :: "r"(smem), "l"(gmem) : "memory");
}
__device__ __forceinline__ void cp_async_commit_wait() {
    asm volatile("cp.async.commit_group;\n\tcp.async.wait_group 0;" ::: "memory");
}

// ---------------------------------------------------------------------------
// K1 (merged): blocks 0..31 fold attention vectors; blocks 32..95 W_j -> fp16.
// ---------------------------------------------------------------------------
__global__ void prep_kernel(const float* __restrict__ W_i,
                            const float* __restrict__ W_j,
                            const float* __restrict__ a_w,
                            const float* __restrict__ a_b) {
    if (blockIdx.x < 32) {
        int warp = blockIdx.x * 8 + (threadIdx.x >> 5);  // 0..255
        int lane = threadIdx.x & 31;
        const float* W  = (warp < 128) ? W_i : W_j;
        const float* av = (warp < 128) ? a_w : a_w + HID;
        int f = warp & 127;
        float4 w4 = ((const float4*)W)[f * 32 + lane];
        float4 a4 = ((const float4*)av)[lane];
        float s = w4.x * a4.x + w4.y * a4.y + w4.z * a4.z + w4.w * a4.w;
        #pragma unroll
        for (int o = 16; o; o >>= 1) s += __shfl_xor_sync(0xffffffffu, s, o);
        if (lane == 0) {
            if (warp < 128) g_u_i[f] = s; else g_u_j[f] = s;
        }
        if (warp == 0 && lane == 0) g_bias = a_b[0];
    } else {
        int i = (blockIdx.x - 32) * 256 + threadIdx.x;   // 16384 total
        g_wf16[i] = __float2half(W_j[i]);
    }
}

// ---------------------------------------------------------------------------
// K2: per-node scalar scores + build fp16 feature table (same h_i pass).
// ---------------------------------------------------------------------------
__global__ void score_kernel(const float* __restrict__ h_i, int N) {
    int warp = blockIdx.x * (blockDim.x >> 5) + (threadIdx.x >> 5);
    int lane = threadIdx.x & 31;
    if (warp >= N) return;
    const float4* h4 = (const float4*)h_i;
    float4 v  = h4[(size_t)warp * 32 + lane];
    float4 ui = ((const float4*)g_u_i)[lane];
    float4 uj = ((const float4*)g_u_j)[lane];

    __half2 p0 = __floats2half2_rn(v.x, v.y);
    __half2 p1 = __floats2half2_rn(v.z, v.w);
    *(uint2*)&g_hf16[(size_t)warp * IN_F + lane * 4] =
        make_uint2(*(uint32_t*)&p0, *(uint32_t*)&p1);

    float a = v.x * ui.x + v.y * ui.y + v.z * ui.z + v.w * ui.w;
    float b = v.x * uj.x + v.y * uj.y + v.z * uj.z + v.w * uj.w;
    #pragma unroll
    for (int o = 16; o; o >>= 1) {
        a += __shfl_xor_sync(0xffffffffu, a, o);
        b += __shfl_xor_sync(0xffffffffu, b, o);
    }
    if (lane == 0) {
        g_s_i[warp] = a;
        g_s_j[warp] = b;
    }
}

// ---------------------------------------------------------------------------
// K3 (fused): gather+softmax+weighted-sum -> smem A tile, then fp16 MMA GEMM.
// Block 256 thr / 8 warps / 64-row tile.
// W streamed into smem by cp.async at entry (overlaps the gather phase).
// Each warp gathers 8 nodes (batch-8 MLP on fp16 table) -> STS fp16 rows.
// ---------------------------------------------------------------------------
#define SMEM_STRIDE 136
#define FUSED_SMEM_BYTES ((64 + 128) * SMEM_STRIDE * 2)

__global__ __launch_bounds__(256) void fused_kernel(
    const int* __restrict__ ctx, float* __restrict__ out, int N) {
    extern __shared__ __half sm[];
    __half* As = sm;                       // [64][136]
    __half* Bs = sm + 64 * SMEM_STRIDE;    // [128][136]

    int row0 = blockIdx.x * 64;
    int tid  = threadIdx.x;
    int warp = tid >> 5;
    int lane = tid & 31;

    // Kick off W -> smem (background): 2048 x 16B, 8 per thread.
    #pragma unroll
    for (int ii = tid; ii < 2048; ii += 256) {
        int kr = ii >> 4, nq = ii & 15;
        cp_async16(smem_u32(&Bs[kr * SMEM_STRIDE + nq * 8]),
                   &g_wf16[kr * HID + nq * 8]);
    }
    asm volatile("cp.async.commit_group;" ::: "memory");

    // Phase 1: gather 8 nodes per warp.
    const uint2* hrow = (const uint2*)g_hf16;
    #pragma unroll 1
    for (int t = 0; t < 8; t++) {
        int node = row0 + warp * 8 + t;
        float4 acc = make_float4(0.f, 0.f, 0.f, 0.f);
        if (node < N) {
            int j = ctx[(size_t)node * NCTX + lane];
            bool valid = (j >= 0);

            float sj = valid ? g_s_j[j] : 0.f;
            float e = g_s_i[node] + sj + g_bias;
            e = (e > 0.f) ? e : ALPHA * e;
            e = valid ? e : NEG_INF;

            float m = e;
            #pragma unroll
            for (int o = 16; o; o >>= 1) m = fmaxf(m, __shfl_xor_sync(0xffffffffu, m, o));
            float p = valid ? __expf(e - m) : 0.f;
            float s = p;
            #pragma unroll
            for (int o = 16; o; o >>= 1) s += __shfl_xor_sync(0xffffffffu, s, o);
            float w = p * ((s > 0.f) ? (1.f / s) : 0.f);

            #pragma unroll
            for (int batch = 0; batch < 4; batch++) {
                int   jq[8];
                float wq[8];
                uint2 vq[8];
                #pragma unroll
                for (int q = 0; q < 8; q++) {
                    int c = batch * 8 + q;
                    jq[q] = __shfl_sync(0xffffffffu, j, c);
                    wq[q] = __shfl_sync(0xffffffffu, w, c);
                }
                #pragma unroll
                for (int q = 0; q < 8; q++) {
                    vq[q] = (jq[q] >= 0) ? hrow[(size_t)jq[q] * 32 + lane]
                                         : make_uint2(0u, 0u);
                }
                #pragma unroll
                for (int q = 0; q < 8; q++) {
                    float2 f0 = __half22float2(*(__half2*)&vq[q].x);
                    float2 f1 = __half22float2(*(__half2*)&vq[q].y);
                    acc.x = fmaf(wq[q], f0.x, acc.x);
                    acc.y = fmaf(wq[q], f0.y, acc.y);
                    acc.z = fmaf(wq[q], f1.x, acc.z);
                    acc.w = fmaf(wq[q], f1.y, acc.w);
                }
            }
        }
        __half2 o0 = __floats2half2_rn(acc.x, acc.y);
        __half2 o1 = __floats2half2_rn(acc.z, acc.w);
        *(uint2*)&As[(warp * 8 + t) * SMEM_STRIDE + lane * 4] =
            make_uint2(*(uint32_t*)&o0, *(uint32_t*)&o1);
    }

    asm volatile("cp.async.wait_group 0;" ::: "memory");
    __syncthreads();

    // Phase 2: MMA.  warp tile 16x64.
    int rbase = (warp & 3) * 16;
    int cbase = (warp >> 2) * 64;

    float acc[8][4];
    #pragma unroll
    for (int t = 0; t < 8; t++)
        #pragma unroll
        for (int q = 0; q < 4; q++) acc[t][q] = 0.f;

    #pragma unroll
    for (int ks = 0; ks < 8; ks++) {
        uint32_t af[4];
        {
            int r = rbase + (lane & 15);
            int k = ks * 16 + (lane >> 4) * 8;
            ldsm_x4(af, smem_u32(&As[r * SMEM_STRIDE + k]));
        }
        #pragma unroll
        for (int nt = 0; nt < 4; nt++) {
            uint32_t bf[4];
            int k = ks * 16 + (lane & 15);
            int n = cbase + nt * 16 + (lane >> 4) * 8;
            ldsm_x4_t(bf, smem_u32(&Bs[k * SMEM_STRIDE + n]));
            mma16816h(acc[2 * nt],     af, bf[0], bf[1]);
            mma16816h(acc[2 * nt + 1], af, bf[2], bf[3]);
        }
    }

    int gid = lane >> 2, tig = lane & 3;
    #pragma unroll
    for (int t = 0; t < 8; t++) {
        int c  = cbase + t * 8 + tig * 2;
        int r1 = row0 + rbase + gid;
        int r2 = r1 + 8;
        if (r1 < N) *(float2*)&out[(size_t)r1 * 128 + c] = make_float2(acc[t][0], acc[t][1]);
        if (r2 < N) *(float2*)&out[(size_t)r2 * 128 + c] = make_float2(acc[t][2], acc[t][3]);
    }
}

// ---------------------------------------------------------------------------
extern "C" void kernel_launch(void* const* d_in, const int* in_sizes, int n_in,
                              void* d_out, int out_size) {
    const float* h_i = (const float*)d_in[0];
    const int*   ctx = (const int*)d_in[1];     // int32
    const float* W_i = (const float*)d_in[2];
    const float* W_j = (const float*)d_in[3];
    const float* a_w = (const float*)d_in[4];
    const float* a_b = (const float*)d_in[5];
    float* out = (float*)d_out;

    int N = in_sizes[0] / IN_F;

    cudaFuncSetAttribute(fused_kernel,
                         cudaFuncAttributeMaxDynamicSharedMemorySize,
                         FUSED_SMEM_BYTES);

    prep_kernel<<<96, 256>>>(W_i, W_j, a_w, a_b);

    int blocks = (N + 7) / 8;
    score_kernel<<<blocks, 256>>>(h_i, N);

    int fused_blocks = (N + 63) / 64;
    fused_kernel<<<fused_blocks, 256, FUSED_SMEM_BYTES>>>(ctx, out, N);
}

// round 15
// speedup vs baseline: 1.2806x; 1.2806x over previous
#include <cuda_runtime.h>
#include <cuda_bf16.h>
#include <cuda_fp16.h>
#include <cstdint>

#define IN_F 128
#define HID 128
#define NCTX 32
#define ALPHA 0.2f
#define NEG_INF -9000000000000000.0f
#define MAXN 20000
#define MAXR 20032

// Scratch (device globals — no allocation allowed)
__device__ __align__(16) float g_u_i[IN_F];
__device__ __align__(16) float g_u_j[IN_F];
__device__ float g_bias;
__device__ float g_s_i[MAXN];
__device__ float g_s_j[MAXN];
__device__ __align__(16) __half g_hf16[(size_t)MAXN * IN_F];   // fp16 feature table
__device__ __align__(16) __half g_af16[(size_t)MAXR * HID];    // fp16 A (weighted sums)
__device__ __align__(16) __half g_wf16[HID * HID];             // fp16 W_j

// ---------------------------------------------------------------------------
// helpers
// ---------------------------------------------------------------------------
__device__ __forceinline__ uint32_t smem_u32(const void* p) {
    return (uint32_t)__cvta_generic_to_shared(p);
}
__device__ __forceinline__ void ldsm_x4(uint32_t* r, uint32_t addr) {
    asm volatile("ldmatrix.sync.aligned.m8n8.x4.shared.b16 {%0,%1,%2,%3}, [%4];"
        : "=r"(r[0]), "=r"(r[1]), "=r"(r[2]), "=r"(r[3]) : "r"(addr));
}
__device__ __forceinline__ void ldsm_x4_t(uint32_t* r, uint32_t addr) {
    asm volatile("ldmatrix.sync.aligned.m8n8.x4.trans.shared.b16 {%0,%1,%2,%3}, [%4];"
        : "=r"(r[0]), "=r"(r[1]), "=r"(r[2]), "=r"(r[3]) : "r"(addr));
}
__device__ __forceinline__ void mma16816h(float* c, const uint32_t* a,
                                          uint32_t b0, uint32_t b1) {
    asm volatile(
        "mma.sync.aligned.m16n8k16.row.col.f32.f16.f16.f32 "
        "{%0,%1,%2,%3}, {%4,%5,%6,%7}, {%8,%9}, {%0,%1,%2,%3};"
        : "+f"(c[0]), "+f"(c[1]), "+f"(c[2]), "+f"(c[3])
        : "r"(a[0]), "r"(a[1]), "r"(a[2]), "r"(a[3]), "r"(b0), "r"(b1));
}

// ---------------------------------------------------------------------------
// K1: fold attention vectors only (32 blocks).
// ---------------------------------------------------------------------------
__global__ void prep_kernel(const float* __restrict__ W_i,
                            const float* __restrict__ W_j,
                            const float* __restrict__ a_w,
                            const float* __restrict__ a_b) {
    int warp = blockIdx.x * 8 + (threadIdx.x >> 5);  // 0..255
    int lane = threadIdx.x & 31;
    const float* W  = (warp < 128) ? W_i : W_j;
    const float* av = (warp < 128) ? a_w : a_w + HID;
    int f = warp & 127;
    float4 w4 = ((const float4*)W)[f * 32 + lane];
    float4 a4 = ((const float4*)av)[lane];
    float s = w4.x * a4.x + w4.y * a4.y + w4.z * a4.z + w4.w * a4.w;
    #pragma unroll
    for (int o = 16; o; o >>= 1) s += __shfl_xor_sync(0xffffffffu, s, o);
    if (lane == 0) {
        if (warp < 128) g_u_i[f] = s; else g_u_j[f] = s;
    }
    if (warp == 0 && lane == 0) g_bias = a_b[0];
}

// ---------------------------------------------------------------------------
// K2: blocks 0..63 convert W_j -> fp16; remaining blocks do per-node scores
// + build the fp16 feature table (same h_i pass).
// ---------------------------------------------------------------------------
__global__ void score_kernel(const float* __restrict__ h_i,
                             const float* __restrict__ W_j, int N) {
    if (blockIdx.x < 64) {
        int i = blockIdx.x * 256 + threadIdx.x;   // 16384 total
        g_wf16[i] = __float2half(W_j[i]);
        return;
    }
    int warp = (blockIdx.x - 64) * 8 + (threadIdx.x >> 5);
    int lane = threadIdx.x & 31;
    if (warp >= N) return;
    const float4* h4 = (const float4*)h_i;
    float4 v  = h4[(size_t)warp * 32 + lane];
    float4 ui = ((const float4*)g_u_i)[lane];
    float4 uj = ((const float4*)g_u_j)[lane];

    __half2 p0 = __floats2half2_rn(v.x, v.y);
    __half2 p1 = __floats2half2_rn(v.z, v.w);
    *(uint2*)&g_hf16[(size_t)warp * IN_F + lane * 4] =
        make_uint2(*(uint32_t*)&p0, *(uint32_t*)&p1);

    float a = v.x * ui.x + v.y * ui.y + v.z * ui.z + v.w * ui.w;
    float b = v.x * uj.x + v.y * uj.y + v.z * uj.z + v.w * uj.w;
    #pragma unroll
    for (int o = 16; o; o >>= 1) {
        a += __shfl_xor_sync(0xffffffffu, a, o);
        b += __shfl_xor_sync(0xffffffffu, b, o);
    }
    if (lane == 0) {
        g_s_i[warp] = a;
        g_s_j[warp] = b;
    }
}

// ---------------------------------------------------------------------------
// K3: gather (fp16 table) + softmax + weighted sum -> fp16 A.
// One warp per node; batches of 8 independent LDG.64.
// ---------------------------------------------------------------------------
__global__ void gather_kernel(const int* __restrict__ ctx, int N) {
    int warp = blockIdx.x * (blockDim.x >> 5) + (threadIdx.x >> 5);
    int lane = threadIdx.x & 31;
    if (warp >= N) return;

    int j = ctx[(size_t)warp * NCTX + lane];
    bool valid = (j >= 0);

    float sj = valid ? g_s_j[j] : 0.f;
    float e = g_s_i[warp] + sj + g_bias;
    e = (e > 0.f) ? e : ALPHA * e;
    e = valid ? e : NEG_INF;

    float m = e;
    #pragma unroll
    for (int o = 16; o; o >>= 1) m = fmaxf(m, __shfl_xor_sync(0xffffffffu, m, o));
    float p = valid ? __expf(e - m) : 0.f;
    float s = p;
    #pragma unroll
    for (int o = 16; o; o >>= 1) s += __shfl_xor_sync(0xffffffffu, s, o);
    float w = p * ((s > 0.f) ? (1.f / s) : 0.f);

    float4 acc = make_float4(0.f, 0.f, 0.f, 0.f);
    const uint2* hrow = (const uint2*)g_hf16;

    #pragma unroll
    for (int batch = 0; batch < 4; batch++) {
        int   jq[8];
        float wq[8];
        uint2 vq[8];
        #pragma unroll
        for (int q = 0; q < 8; q++) {
            int c = batch * 8 + q;
            jq[q] = __shfl_sync(0xffffffffu, j, c);
            wq[q] = __shfl_sync(0xffffffffu, w, c);
        }
        #pragma unroll
        for (int q = 0; q < 8; q++) {
            vq[q] = (jq[q] >= 0) ? hrow[(size_t)jq[q] * 32 + lane]
                                 : make_uint2(0u, 0u);
        }
        #pragma unroll
        for (int q = 0; q < 8; q++) {
            float2 f0 = __half22float2(*(__half2*)&vq[q].x);
            float2 f1 = __half22float2(*(__half2*)&vq[q].y);
            acc.x = fmaf(wq[q], f0.x, acc.x);
            acc.y = fmaf(wq[q], f0.y, acc.y);
            acc.z = fmaf(wq[q], f1.x, acc.z);
            acc.w = fmaf(wq[q], f1.y, acc.w);
        }
    }

    __half2 o0 = __floats2half2_rn(acc.x, acc.y);
    __half2 o1 = __floats2half2_rn(acc.z, acc.w);
    *(uint2*)&g_af16[(size_t)warp * HID + lane * 4] =
        make_uint2(*(uint32_t*)&o0, *(uint32_t*)&o1);
}

// ---------------------------------------------------------------------------
// K4 (v11): out = A @ W, fp16 tensor cores, ONE WAVE.
// Tile 128 rows x 128 cols (grid 157), 256 thr / 8 warps; warp tile 32x64.
// A tile (34KB) + full W (34KB) in 70KB smem, one sync, unrolled MMA.
// ---------------------------------------------------------------------------
#define SMEM_STRIDE 136
#define GEMM_SMEM_BYTES ((128 + 128) * SMEM_STRIDE * 2)

__global__ __launch_bounds__(256) void mma_gemm_kernel(float* __restrict__ out,
                                                       int N) {
    extern __shared__ __half sm[];
    __half* As = sm;                        // [128][136]
    __half* Bs = sm + 128 * SMEM_STRIDE;    // [128][136]

    int row0 = blockIdx.x * 128;
    int tid  = threadIdx.x;
    int warp = tid >> 5;
    int lane = tid & 31;
    int rbase = (warp & 3) * 32;
    int cbase = (warp >> 2) * 64;

    // Load A tile: 128 rows x 128 k = 2048 uint4, 8 per thread.
    #pragma unroll
    for (int ii = tid; ii < 2048; ii += 256) {
        int r = ii >> 4, q = ii & 15;
        int gr = row0 + r;
        uint4 v = make_uint4(0, 0, 0, 0);
        if (gr < N) v = *(const uint4*)&g_af16[(size_t)gr * HID + q * 8];
        *(uint4*)&As[r * SMEM_STRIDE + q * 8] = v;
    }
    // Load full W: 2048 uint4, 8 per thread.
    #pragma unroll
    for (int ii = tid; ii < 2048; ii += 256) {
        int kr = ii >> 4, nq = ii & 15;
        *(uint4*)&Bs[kr * SMEM_STRIDE + nq * 8] =
            *(const uint4*)&g_wf16[kr * HID + nq * 8];
    }
    __syncthreads();

    float acc[2][8][4];
    #pragma unroll
    for (int rr = 0; rr < 2; rr++)
        #pragma unroll
        for (int t = 0; t < 8; t++)
            #pragma unroll
            for (int q = 0; q < 4; q++) acc[rr][t][q] = 0.f;

    #pragma unroll
    for (int ks = 0; ks < 8; ks++) {
        uint32_t af0[4], af1[4];
        {
            int k = ks * 16 + (lane >> 4) * 8;
            int r0 = rbase + (lane & 15);
            ldsm_x4(af0, smem_u32(&As[r0 * SMEM_STRIDE + k]));
            ldsm_x4(af1, smem_u32(&As[(r0 + 16) * SMEM_STRIDE + k]));
        }
        #pragma unroll
        for (int nt = 0; nt < 4; nt++) {
            uint32_t bf[4];
            int k = ks * 16 + (lane & 15);
            int n = cbase + nt * 16 + (lane >> 4) * 8;
            ldsm_x4_t(bf, smem_u32(&Bs[k * SMEM_STRIDE + n]));
            mma16816h(acc[0][2 * nt],     af0, bf[0], bf[1]);
            mma16816h(acc[0][2 * nt + 1], af0, bf[2], bf[3]);
            mma16816h(acc[1][2 * nt],     af1, bf[0], bf[1]);
            mma16816h(acc[1][2 * nt + 1], af1, bf[2], bf[3]);
        }
    }

    int gid = lane >> 2, tig = lane & 3;
    #pragma unroll
    for (int rr = 0; rr < 2; rr++) {
        #pragma unroll
        for (int t = 0; t < 8; t++) {
            int c  = cbase + t * 8 + tig * 2;
            int r1 = row0 + rbase + rr * 16 + gid;
            int r2 = r1 + 8;
            if (r1 < N) *(float2*)&out[(size_t)r1 * 128 + c] =
                make_float2(acc[rr][t][0], acc[rr][t][1]);
            if (r2 < N) *(float2*)&out[(size_t)r2 * 128 + c] =
                make_float2(acc[rr][t][2], acc[rr][t][3]);
        }
    }
}

// ---------------------------------------------------------------------------
extern "C" void kernel_launch(void* const* d_in, const int* in_sizes, int n_in,
                              void* d_out, int out_size) {
    const float* h_i = (const float*)d_in[0];
    const int*   ctx = (const int*)d_in[1];     // int32
    const float* W_i = (const float*)d_in[2];
    const float* W_j = (const float*)d_in[3];
    const float* a_w = (const float*)d_in[4];
    const float* a_b = (const float*)d_in[5];
    float* out = (float*)d_out;

    int N = in_sizes[0] / IN_F;

    cudaFuncSetAttribute(mma_gemm_kernel,
                         cudaFuncAttributeMaxDynamicSharedMemorySize,
                         GEMM_SMEM_BYTES);

    prep_kernel<<<32, 256>>>(W_i, W_j, a_w, a_b);

    int sblocks = 64 + (N + 7) / 8;
    score_kernel<<<sblocks, 256>>>(h_i, W_j, N);

    int gblocks = (N + 7) / 8;
    gather_kernel<<<gblocks, 256>>>(ctx, N);

    int gemm_blocks = (N + 127) / 128;
    mma_gemm_kernel<<<gemm_blocks, 256, GEMM_SMEM_BYTES>>>(out, N);
}

// round 17
// speedup vs baseline: 1.3279x; 1.0369x over previous
#include <cuda_runtime.h>
#include <cuda_bf16.h>
#include <cuda_fp16.h>
#include <cstdint>

#define IN_F 128
#define HID 128
#define NCTX 32
#define ALPHA 0.2f
#define NEG_INF -9000000000000000.0f
#define MAXN 20000
#define MAXR 20032   // 313 * 64

// Scratch (device globals — no allocation allowed)
__device__ __align__(16) float g_u_i[IN_F];
__device__ __align__(16) float g_u_j[IN_F];
__device__ float g_bias;
__device__ int   g_pflag;                                     // fold-done flag
__device__ float g_s_i[MAXN];
__device__ float g_s_j[MAXN];
__device__ __align__(16) __half g_wh16[(size_t)MAXR * HID];   // Wh = h @ W_j (fp16)

// ---------------------------------------------------------------------------
// mma/ldmatrix helpers
// ---------------------------------------------------------------------------
__device__ __forceinline__ uint32_t smem_u32(const void* p) {
    return (uint32_t)__cvta_generic_to_shared(p);
}
__device__ __forceinline__ void ldsm_x4(uint32_t* r, uint32_t addr) {
    asm volatile("ldmatrix.sync.aligned.m8n8.x4.shared.b16 {%0,%1,%2,%3}, [%4];"
        : "=r"(r[0]), "=r"(r[1]), "=r"(r[2]), "=r"(r[3]) : "r"(addr));
}
__device__ __forceinline__ void ldsm_x4_t(uint32_t* r, uint32_t addr) {
    asm volatile("ldmatrix.sync.aligned.m8n8.x4.trans.shared.b16 {%0,%1,%2,%3}, [%4];"
        : "=r"(r[0]), "=r"(r[1]), "=r"(r[2]), "=r"(r[3]) : "r"(addr));
}
__device__ __forceinline__ void mma16816h(float* c, const uint32_t* a,
                                          uint32_t b0, uint32_t b1) {
    asm volatile(
        "mma.sync.aligned.m16n8k16.row.col.f32.f16.f16.f32 "
        "{%0,%1,%2,%3}, {%4,%5,%6,%7}, {%8,%9}, {%0,%1,%2,%3};"
        : "+f"(c[0]), "+f"(c[1]), "+f"(c[2]), "+f"(c[3])
        : "r"(a[0]), "r"(a[1]), "r"(a[2]), "r"(a[3]), "r"(b0), "r"(b1));
}

// ---------------------------------------------------------------------------
// K1 (merged): blocks [0, gb)      : GEMM tiles  Wh = h @ W_j   (fp16 mma)
//              blocks [gb, gb+32)  : fold attention vectors, raise flag
//              blocks [gb+32, ...) : per-node scores (spin on flag)
// GEMM depends only on raw inputs -> runs concurrently with fold/score.
// ---------------------------------------------------------------------------
#define SMEM_STRIDE 136
#define MID_SMEM_BYTES ((64 + 128) * SMEM_STRIDE * 2)   // 52224

__global__ __launch_bounds__(256) void mid_kernel(
    const float* __restrict__ h_i,
    const float* __restrict__ W_i,
    const float* __restrict__ W_j,
    const float* __restrict__ a_w,
    const float* __restrict__ a_b,
    int N, int gb) {
    extern __shared__ __half sm[];
    int tid  = threadIdx.x;
    int warp = tid >> 5;
    int lane = tid & 31;

    if ((int)blockIdx.x < gb) {
        // ---------------- GEMM tile: rows [row0, row0+64) ----------------
        __half* As = sm;                       // [64][136]
        __half* Bs = sm + 64 * SMEM_STRIDE;    // [128][136]
        int row0 = blockIdx.x * 64;

        const float4* h4 = (const float4*)h_i;
        const float4* w4 = (const float4*)W_j;

        // A: 64 rows x 128 cols fp32 -> fp16.  2048 float4, 8/thread.
        #pragma unroll
        for (int ii = tid; ii < 2048; ii += 256) {
            int r = ii >> 5, q = ii & 31;
            int gr = row0 + r;
            float4 v = make_float4(0.f, 0.f, 0.f, 0.f);
            if (gr < N) v = h4[(size_t)gr * 32 + q];
            __half2 a0 = __floats2half2_rn(v.x, v.y);
            __half2 a1 = __floats2half2_rn(v.z, v.w);
            *(uint2*)&As[r * SMEM_STRIDE + q * 4] =
                make_uint2(*(uint32_t*)&a0, *(uint32_t*)&a1);
        }
        // B: W_j [k][n] fp32 -> fp16.  4096 float4, 16/thread.
        #pragma unroll
        for (int ii = tid; ii < 4096; ii += 256) {
            int kr = ii >> 5, q = ii & 31;
            float4 v = w4[(size_t)kr * 32 + q];
            __half2 b0 = __floats2half2_rn(v.x, v.y);
            __half2 b1 = __floats2half2_rn(v.z, v.w);
            *(uint2*)&Bs[kr * SMEM_STRIDE + q * 4] =
                make_uint2(*(uint32_t*)&b0, *(uint32_t*)&b1);
        }
        __syncthreads();

        int rbase = (warp & 3) * 16;
        int cbase = (warp >> 2) * 64;

        float acc[8][4];
        #pragma unroll
        for (int t = 0; t < 8; t++)
            #pragma unroll
            for (int q = 0; q < 4; q++) acc[t][q] = 0.f;

        #pragma unroll
        for (int ks = 0; ks < 8; ks++) {
            uint32_t af[4];
            {
                int r = rbase + (lane & 15);
                int k = ks * 16 + (lane >> 4) * 8;
                ldsm_x4(af, smem_u32(&As[r * SMEM_STRIDE + k]));
            }
            #pragma unroll
            for (int nt = 0; nt < 4; nt++) {
                uint32_t bf[4];
                int k = ks * 16 + (lane & 15);
                int n = cbase + nt * 16 + (lane >> 4) * 8;
                ldsm_x4_t(bf, smem_u32(&Bs[k * SMEM_STRIDE + n]));
                mma16816h(acc[2 * nt],     af, bf[0], bf[1]);
                mma16816h(acc[2 * nt + 1], af, bf[2], bf[3]);
            }
        }

        // epilogue: Wh fp16
        int gid = lane >> 2, tig = lane & 3;
        #pragma unroll
        for (int t = 0; t < 8; t++) {
            int c  = cbase + t * 8 + tig * 2;
            int r1 = row0 + rbase + gid;
            int r2 = r1 + 8;
            if (r1 < N) {
                __half2 o = __floats2half2_rn(acc[t][0], acc[t][1]);
                *(__half2*)&g_wh16[(size_t)r1 * 128 + c] = o;
            }
            if (r2 < N) {
                __half2 o = __floats2half2_rn(acc[t][2], acc[t][3]);
                *(__half2*)&g_wh16[(size_t)r2 * 128 + c] = o;
            }
        }
        return;
    }

    if ((int)blockIdx.x < gb + 32) {
        // ---------------- fold attention vectors ----------------
        int fw = (blockIdx.x - gb) * 8 + warp;   // 0..255
        const float* W  = (fw < 128) ? W_i : W_j;
        const float* av = (fw < 128) ? a_w : a_w + HID;
        int f = fw & 127;
        float4 w4 = ((const float4*)W)[f * 32 + lane];
        float4 a4 = ((const float4*)av)[lane];
        float s = w4.x * a4.x + w4.y * a4.y + w4.z * a4.z + w4.w * a4.w;
        #pragma unroll
        for (int o = 16; o; o >>= 1) s += __shfl_xor_sync(0xffffffffu, s, o);
        if (lane == 0) {
            if (fw < 128) g_u_i[f] = s; else g_u_j[f] = s;
        }
        if (fw == ((int)blockIdx.x - gb) * 8 && lane == 0 && warp == 0)
            g_bias = a_b[0];
        __syncthreads();
        if (tid == 0) {
            __threadfence();
            atomicAdd(&g_pflag, 1);
        }
        return;
    }

    // ---------------- per-node scores (spin on fold flag) ----------------
    if (tid == 0) {
        while (atomicAdd(&g_pflag, 0) < 32) { }
    }
    __syncthreads();
    __threadfence();

    int node = (blockIdx.x - gb - 32) * 8 + warp;
    if (node >= N) return;
    const float4* h4 = (const float4*)h_i;
    float4 v  = h4[(size_t)node * 32 + lane];
    float4 ui = ((const float4*)g_u_i)[lane];
    float4 uj = ((const float4*)g_u_j)[lane];
    float a = v.x * ui.x + v.y * ui.y + v.z * ui.z + v.w * ui.w;
    float b = v.x * uj.x + v.y * uj.y + v.z * uj.z + v.w * uj.w;
    #pragma unroll
    for (int o = 16; o; o >>= 1) {
        a += __shfl_xor_sync(0xffffffffu, a, o);
        b += __shfl_xor_sync(0xffffffffu, b, o);
    }
    if (lane == 0) {
        g_s_i[node] = a;
        g_s_j[node] = b;
    }
}

// ---------------------------------------------------------------------------
// K2: gather -> FINAL OUTPUT.  out[n] = sum_c attn_c * Wh[j_c]
// One warp per node; batches of 8 independent LDG.64 on the fp16 Wh table.
// Block 0 resets the fold flag for the next graph replay.
// ---------------------------------------------------------------------------
__global__ void gather_kernel(const int* __restrict__ ctx,
                              float* __restrict__ out, int N) {
    if (blockIdx.x == 0 && threadIdx.x == 0) g_pflag = 0;

    int warp = blockIdx.x * (blockDim.x >> 5) + (threadIdx.x >> 5);
    int lane = threadIdx.x & 31;
    if (warp >= N) return;

    int j = ctx[(size_t)warp * NCTX + lane];
    bool valid = (j >= 0);

    float sj = valid ? g_s_j[j] : 0.f;
    float e = g_s_i[warp] + sj + g_bias;
    e = (e > 0.f) ? e : ALPHA * e;
    e = valid ? e : NEG_INF;

    float m = e;
    #pragma unroll
    for (int o = 16; o; o >>= 1) m = fmaxf(m, __shfl_xor_sync(0xffffffffu, m, o));
    float p = valid ? __expf(e - m) : 0.f;
    float s = p;
    #pragma unroll
    for (int o = 16; o; o >>= 1) s += __shfl_xor_sync(0xffffffffu, s, o);
    float w = p * ((s > 0.f) ? (1.f / s) : 0.f);

    float4 acc = make_float4(0.f, 0.f, 0.f, 0.f);
    const uint2* whrow = (const uint2*)g_wh16;   // 4 halves per uint2; 32/row

    #pragma unroll
    for (int batch = 0; batch < 4; batch++) {
        int   jq[8];
        float wq[8];
        uint2 vq[8];
        #pragma unroll
        for (int q = 0; q < 8; q++) {
            int c = batch * 8 + q;
            jq[q] = __shfl_sync(0xffffffffu, j, c);
            wq[q] = __shfl_sync(0xffffffffu, w, c);
        }
        #pragma unroll
        for (int q = 0; q < 8; q++) {
            vq[q] = (jq[q] >= 0) ? whrow[(size_t)jq[q] * 32 + lane]
                                 : make_uint2(0u, 0u);
        }
        #pragma unroll
        for (int q = 0; q < 8; q++) {
            float2 f0 = __half22float2(*(__half2*)&vq[q].x);
            float2 f1 = __half22float2(*(__half2*)&vq[q].y);
            acc.x = fmaf(wq[q], f0.x, acc.x);
            acc.y = fmaf(wq[q], f0.y, acc.y);
            acc.z = fmaf(wq[q], f1.x, acc.z);
            acc.w = fmaf(wq[q], f1.y, acc.w);
        }
    }

    *(float4*)&out[(size_t)warp * 128 + lane * 4] = acc;
}

// ---------------------------------------------------------------------------
extern "C" void kernel_launch(void* const* d_in, const int* in_sizes, int n_in,
                              void* d_out, int out_size) {
    const float* h_i = (const float*)d_in[0];
    const int*   ctx = (const int*)d_in[1];     // int32
    const float* W_i = (const float*)d_in[2];
    const float* W_j = (const float*)d_in[3];
    const float* a_w = (const float*)d_in[4];
    const float* a_b = (const float*)d_in[5];
    float* out = (float*)d_out;

    int N = in_sizes[0] / IN_F;

    cudaFuncSetAttribute(mid_kernel,
                         cudaFuncAttributeMaxDynamicSharedMemorySize,
                         MID_SMEM_BYTES);

    int gb = (N + 63) / 64;                 // gemm tiles
    int sb = (N + 7) / 8;                   // score blocks
    mid_kernel<<<gb + 32 + sb, 256, MID_SMEM_BYTES>>>(h_i, W_i, W_j, a_w, a_b,
                                                      N, gb);

    int gblocks = (N + 7) / 8;
    gather_kernel<<<gblocks, 256>>>(ctx, out, N);
}